// round 11
// baseline (speedup 1.0000x reference)
#include <cuda_runtime.h>
#include <cuda_fp16.h>
#include <cstdint>
#include <cstddef>

#define B_   64
#define S_   512
#define E_   300
#define EP_  304
#define M_   32768

__device__ float g_x[M_ * EP_];
__device__ float g_w0pad[2][1024 * EP_];
__device__ float g_gx0[M_ * 2048];
__device__ float g_h1 [M_ * 512];
__device__ float g_gx1[M_ * 2048];
__device__ float g_h2 [M_ * 512];
__device__ __half g_hbufh[2][2][B_ * 256];
__device__ float g_err[M_];
__device__ unsigned g_c1[8 * 32];
__device__ unsigned g_croot[2 * 32];

#define FMA2(acc, a, b) \
    asm("fma.rn.f32x2 %0, %1, %2, %0;" : "+l"(acc) : "l"(a), "l"(b))
#define PACK2(out, x) \
    asm("mov.b64 %0, {%1, %1};" : "=l"(out) : "f"(x))
#define UNPACK2(lo, hi, v) \
    asm("mov.b64 {%0, %1}, %2;" : "=f"(lo), "=f"(hi) : "l"(v))

__device__ __forceinline__ float sigm(float x) { return 1.0f / (1.0f + expf(-x)); }

// e^{-ax} for ax >= 0, FMA/ALU only. err ~1.2e-7 rel.
__device__ __forceinline__ float exp_neg(float ax) {
    float t = fmaxf(-ax * 1.44269504088896f, -80.0f);
    float r = t + 12582912.0f;
    int   n = __float_as_int(r) - 0x4B400000;
    float f = t - (r - 12582912.0f);
    float y = f * 0.693147180559945f;
    float p = 1.3888889e-3f;
    p = fmaf(p, y, 8.3333333e-3f);
    p = fmaf(p, y, 4.1666667e-2f);
    p = fmaf(p, y, 1.6666667e-1f);
    p = fmaf(p, y, 0.5f);
    p = fmaf(p, y, 1.0f);
    p = fmaf(p, y, 1.0f);
    return __int_as_float(__float_as_int(p) + (n << 23));
}
__device__ __forceinline__ float recip12(float d) {
    float r = fmaf(-0.45710678f, d, 1.45710678f);
    r = fmaf(r, fmaf(-d, r, 1.0f), r);
    r = fmaf(r, fmaf(-d, r, 1.0f), r);
    r = fmaf(r, fmaf(-d, r, 1.0f), r);
    return r;
}
__device__ __forceinline__ float sigm_f(float x) {
    float u = exp_neg(fabsf(x));
    float r = recip12(1.0f + u);
    return x >= 0.0f ? r : u * r;
}
__device__ __forceinline__ float tanh_f(float x) {
    float u = exp_neg(2.0f * fabsf(x));
    float m = (1.0f - u) * recip12(1.0f + u);
    return x >= 0.0f ? m : -m;
}

__global__ void zerocnt_kernel() {
    int i = threadIdx.x;
    if (i < 8 * 32) g_c1[i] = 0u;
    if (i < 2) g_croot[i * 32] = 0u;
}

__global__ void gather_kernel(const int* __restrict__ ids, const float* __restrict__ emb) {
    int m = blockIdx.x, s = m >> 6, b = m & 63;
    int id = ids[b * S_ + s];
    const float* src = emb + (size_t)id * E_;
    float* dst = g_x + (size_t)m * EP_;
    for (int e = threadIdx.x; e < EP_; e += blockDim.x)
        dst[e] = (e < E_) ? src[e] : 0.0f;
}

__global__ void padw_kernel(const float* __restrict__ wf, const float* __restrict__ wb) {
    int row = blockIdx.x & 1023, dir = blockIdx.x >> 10;
    const float* src = (dir ? wb : wf) + (size_t)row * E_;
    float* dst = g_w0pad[dir] + (size_t)row * EP_;
    for (int e = threadIdx.x; e < EP_; e += blockDim.x)
        dst[e] = (e < E_) ? src[e] : 0.0f;
}

// BM=128,BN=64,BK=16, double-buffered, fma.rn.f32x2 inner.
__global__ void sgemm_kernel(int layer, int dir,
                             const float* __restrict__ Wext,
                             const float* __restrict__ b1,
                             const float* __restrict__ b2) {
    const float* A; const float* W; float* C; int lda, K;
    if (layer == 0) { A = g_x;  lda = EP_; K = EP_; W = g_w0pad[dir]; C = g_gx0; }
    else            { A = g_h1; lda = 512; K = 512; W = Wext;         C = g_gx1; }
    const int coloff = dir << 10;

    __shared__ float As[2][16][132];
    __shared__ float Bs[2][16][68];

    const int tid = threadIdx.x;
    const int m0 = blockIdx.y * 128, n0 = blockIdx.x * 64;
    const int tx = tid & 15, ty = tid >> 4;
    const int arow = tid >> 2, acol = (tid & 3) * 4;

    unsigned long long acc2[4][4];
#pragma unroll
    for (int i = 0; i < 4; ++i)
#pragma unroll
        for (int j = 0; j < 4; ++j) acc2[i][j] = 0ULL;

    const int nIter = K >> 4;
    {
        float4 a0 = *(const float4*)(A + (size_t)(m0 + arow)      * lda + acol);
        float4 a1 = *(const float4*)(A + (size_t)(m0 + arow + 64) * lda + acol);
        float4 bv = *(const float4*)(W + (size_t)(n0 + arow)      * lda + acol);
        As[0][acol + 0][arow] = a0.x; As[0][acol + 1][arow] = a0.y;
        As[0][acol + 2][arow] = a0.z; As[0][acol + 3][arow] = a0.w;
        As[0][acol + 0][arow + 64] = a1.x; As[0][acol + 1][arow + 64] = a1.y;
        As[0][acol + 2][arow + 64] = a1.z; As[0][acol + 3][arow + 64] = a1.w;
        Bs[0][acol + 0][arow] = bv.x; Bs[0][acol + 1][arow] = bv.y;
        Bs[0][acol + 2][arow] = bv.z; Bs[0][acol + 3][arow] = bv.w;
    }
    __syncthreads();

    for (int it = 0; it < nIter; ++it) {
        const int cur = it & 1, nxt = cur ^ 1;
        const bool more = (it + 1 < nIter);
        float4 na0, na1, nbv;
        if (more) {
            const int k0 = (it + 1) << 4;
            na0 = *(const float4*)(A + (size_t)(m0 + arow)      * lda + k0 + acol);
            na1 = *(const float4*)(A + (size_t)(m0 + arow + 64) * lda + k0 + acol);
            nbv = *(const float4*)(W + (size_t)(n0 + arow)      * lda + k0 + acol);
        }
#pragma unroll
        for (int k = 0; k < 16; ++k) {
            const float* ar = &As[cur][k][ty * 8];
            ulonglong2 a01 = *(const ulonglong2*)ar;
            ulonglong2 a23 = *(const ulonglong2*)(ar + 4);
            float4 bw = *(const float4*)&Bs[cur][k][tx * 4];
            unsigned long long bd[4];
            PACK2(bd[0], bw.x); PACK2(bd[1], bw.y);
            PACK2(bd[2], bw.z); PACK2(bd[3], bw.w);
#pragma unroll
            for (int j = 0; j < 4; ++j) {
                FMA2(acc2[0][j], a01.x, bd[j]);
                FMA2(acc2[1][j], a01.y, bd[j]);
                FMA2(acc2[2][j], a23.x, bd[j]);
                FMA2(acc2[3][j], a23.y, bd[j]);
            }
        }
        if (more) {
            As[nxt][acol + 0][arow] = na0.x; As[nxt][acol + 1][arow] = na0.y;
            As[nxt][acol + 2][arow] = na0.z; As[nxt][acol + 3][arow] = na0.w;
            As[nxt][acol + 0][arow + 64] = na1.x; As[nxt][acol + 1][arow + 64] = na1.y;
            As[nxt][acol + 2][arow + 64] = na1.z; As[nxt][acol + 3][arow + 64] = na1.w;
            Bs[nxt][acol + 0][arow] = nbv.x; Bs[nxt][acol + 1][arow] = nbv.y;
            Bs[nxt][acol + 2][arow] = nbv.z; Bs[nxt][acol + 3][arow] = nbv.w;
        }
        __syncthreads();
    }

    const int ng = n0 + tx * 4;
    float bsum[4];
#pragma unroll
    for (int j = 0; j < 4; ++j) bsum[j] = b1[ng + j] + b2[ng + j];
#pragma unroll
    for (int p = 0; p < 4; ++p) {
        float lo[4], hi[4];
#pragma unroll
        for (int j = 0; j < 4; ++j) UNPACK2(lo[j], hi[j], acc2[p][j]);
        int m = m0 + ty * 8 + p * 2;
        float4 o0, o1;
        o0.x = lo[0] + bsum[0]; o0.y = lo[1] + bsum[1];
        o0.z = lo[2] + bsum[2]; o0.w = lo[3] + bsum[3];
        o1.x = hi[0] + bsum[0]; o1.y = hi[1] + bsum[1];
        o1.z = hi[2] + bsum[2]; o1.w = hi[3] + bsum[3];
        *(float4*)(C + (size_t)m * 2048 + coloff + ng) = o0;
        *(float4*)(C + (size_t)(m + 1) * 2048 + coloff + ng) = o1;
    }
}

// Per-direction hierarchical barrier: 4 groups of 16 per dir + per-dir root.
__device__ __forceinline__ void gbar(int tid, unsigned grp, unsigned k) {
    __threadfence();
    __syncthreads();
    if (tid == 0) {
        unsigned a = atomicAdd(&g_c1[grp * 32], 1u) + 1u;
        unsigned rd = (grp >> 2) * 32;
        if (a == 16u * k) atomicAdd(&g_croot[rd], 1u);
        while (*(volatile unsigned*)&g_croot[rd] < 4u * k) { }
        __threadfence();
    }
    __syncthreads();
}

// Persistent bi-LSTM: 128 CTAs, 256 thr. CTA = (dir, 4 dims). W_hh slice fully
// register-resident; h exchanged via global fp16; FMA-only transcendentals.
// smem floats: Hs[64][268] @0, Gxs[2][64][20] @17152, Gs[64][20] @19712
#define LSTM_SMEM_FLOATS 20992
#define LSTM_SMEM_BYTES (LSTM_SMEM_FLOATS * 4)

__global__ void __launch_bounds__(256, 1)
lstm_kernel(int layer, const float* __restrict__ whh_f,
            const float* __restrict__ whh_b) {
    extern __shared__ float smf[];
    float* Hs  = smf;
    float* Gxs = smf + 17152;
    float* Gs  = smf + 19712;

    const int tid = threadIdx.x;
    const int dir = blockIdx.x >> 6;
    const int j0  = (blockIdx.x & 63) << 2;
    const unsigned grp = (unsigned)blockIdx.x >> 4;
    const float* whh  = dir ? whh_b : whh_f;
    const float* gx   = layer ? g_gx1 : g_gx0;
    float*       hout = layer ? g_h2  : g_h1;
    __half* hb0 = &g_hbufh[0][dir][0];
    __half* hb1 = &g_hbufh[1][dir][0];

    const int kid = tid & 7;
    const int a8  = (tid >> 3) & 3;   // gate
    const int w   = tid >> 5;          // warp -> bats w*8..w*8+7

    // W slice fully in registers: gate a8, dims j0..j0+3, k-slice kid*4+c*32+(0..3)
    ulonglong2 wreg[4][8];
#pragma unroll
    for (int i = 0; i < 4; ++i)
#pragma unroll
        for (int c = 0; c < 8; ++c)
            wreg[i][c] = *(const ulonglong2*)(whh
                + (size_t)((a8 << 8) + j0 + i) * 256 + (c << 5) + (kid << 2));

    // zero h(0) fp16 buffer 0 (2048 uint4)
    {
        uint4 z = make_uint4(0, 0, 0, 0);
        uint4* hz = (uint4*)hb0;
#pragma unroll
        for (int i = 0; i < 8; ++i) hz[(i << 8) + tid] = z;
    }
    const int pb = tid >> 2, pq = tid & 3;   // gx prefetch: bat, gate
    {
        int s0 = dir ? 511 : 0;
        float4 gv = *(const float4*)(gx + (size_t)(s0 * 64 + pb) * 2048
                                       + (dir << 10) + (pq << 8) + j0);
        *(float4*)(Gxs + pb * 20 + pq * 4) = gv;
    }
    unsigned kbar = 1u;
    gbar(tid, grp, kbar);

    const int sb = tid & 63, sq = tid >> 6;   // staging: bat, dim-quarter
    const int ujj = tid & 3, ubat = tid >> 2; // update cell
    float creg = 0.0f;

    for (int t = 0; t < 512; ++t) {
        const int s = dir ? 511 - t : t;
        const int cur = t & 1, nxt = cur ^ 1;
        const __half* hsrc = cur ? hb1 : hb0;
        __half*       hdst = cur ? hb0 : hb1;

        {   // stage h(t): fp16 global -> fp32 smem Hs[bat][268]
            const uint4* hg = (const uint4*)hsrc + (sb << 5) + (sq << 3);
            float* hsb = Hs + sb * 268 + (sq << 6);
#pragma unroll
            for (int i = 0; i < 8; ++i) {
                uint4 v = __ldcg(hg + i);
                float2 f0 = __half22float2(*(__half2*)&v.x);
                float2 f1 = __half22float2(*(__half2*)&v.y);
                float2 f2 = __half22float2(*(__half2*)&v.z);
                float2 f3 = __half22float2(*(__half2*)&v.w);
                float4 o0, o1;
                o0.x = f0.x; o0.y = f0.y; o0.z = f1.x; o0.w = f1.y;
                o1.x = f2.x; o1.y = f2.y; o1.z = f3.x; o1.w = f3.y;
                *(float4*)(hsb + (i << 3)) = o0;
                *(float4*)(hsb + (i << 3) + 4) = o1;
            }
        }
        float4 gv;   // prefetch gx(t+1)
        {
            int t2 = (t < 511) ? t + 1 : t;
            int s2 = dir ? 511 - t2 : t2;
            gv = *(const float4*)(gx + (size_t)(s2 * 64 + pb) * 2048
                                    + (dir << 10) + (pq << 8) + j0);
        }
        __syncthreads();

        // dot in two bat-passes of 4; W from registers; reduce-scatter per pass
#pragma unroll
        for (int p = 0; p < 2; ++p) {
            unsigned long long acc[4][4];
#pragma unroll
            for (int i = 0; i < 4; ++i)
#pragma unroll
                for (int j = 0; j < 4; ++j) acc[i][j] = 0ULL;

            const float* hbase = Hs + ((w << 3) + (p << 2)) * 268 + (kid << 2);
#pragma unroll
            for (int c = 0; c < 8; ++c) {
                const int ko = c << 5;
#pragma unroll
                for (int j = 0; j < 4; ++j) {
                    ulonglong2 hv = *(const ulonglong2*)(hbase + j * 268 + ko);
                    FMA2(acc[0][j], wreg[0][c].x, hv.x); FMA2(acc[0][j], wreg[0][c].y, hv.y);
                    FMA2(acc[1][j], wreg[1][c].x, hv.x); FMA2(acc[1][j], wreg[1][c].y, hv.y);
                    FMA2(acc[2][j], wreg[2][c].x, hv.x); FMA2(acc[2][j], wreg[2][c].y, hv.y);
                    FMA2(acc[3][j], wreg[3][c].x, hv.x); FMA2(acc[3][j], wreg[3][c].y, hv.y);
                }
            }
            float g4[4];
#pragma unroll
            for (int i = 0; i < 4; ++i) {
                float v0, v1, v2, v3, lo, hi;
                UNPACK2(lo, hi, acc[i][0]); v0 = lo + hi;
                UNPACK2(lo, hi, acc[i][1]); v1 = lo + hi;
                UNPACK2(lo, hi, acc[i][2]); v2 = lo + hi;
                UNPACK2(lo, hi, acc[i][3]); v3 = lo + hi;
                v0 += __shfl_xor_sync(0xffffffffu, v0, 4);
                v1 += __shfl_xor_sync(0xffffffffu, v1, 4);
                v2 += __shfl_xor_sync(0xffffffffu, v2, 4);
                v3 += __shfl_xor_sync(0xffffffffu, v3, 4);
                float y0 = __shfl_xor_sync(0xffffffffu, v0, 2);
                float y1 = __shfl_xor_sync(0xffffffffu, v1, 2);
                float y2 = __shfl_xor_sync(0xffffffffu, v2, 2);
                float y3 = __shfl_xor_sync(0xffffffffu, v3, 2);
                float u0 = (kid & 2) ? (v2 + y2) : (v0 + y0);
                float u1 = (kid & 2) ? (v3 + y3) : (v1 + y1);
                float q0 = __shfl_xor_sync(0xffffffffu, u0, 1);
                float q1 = __shfl_xor_sync(0xffffffffu, u1, 1);
                g4[i] = (kid & 1) ? (u1 + q1) : (u0 + q0);
            }
            if ((kid >> 2) == p) {
                float4 o; o.x = g4[0]; o.y = g4[1]; o.z = g4[2]; o.w = g4[3];
                *(float4*)(Gs + ((w << 3) + (p << 2) + (kid & 3)) * 20 + (a8 << 2)) = o;
            }
        }
        *(float4*)(Gxs + nxt * 1280 + pb * 20 + pq * 4) = gv;
        __syncthreads();

        // update cell (dim j0+ujj, bat ubat)
        {
            const float* gsb = Gs + ubat * 20;
            const float* gxb = Gxs + cur * 1280 + ubat * 20;
            float gi = gsb[ujj]      + gxb[ujj];
            float gf = gsb[4 + ujj]  + gxb[4 + ujj];
            float gg = gsb[8 + ujj]  + gxb[8 + ujj];
            float go = gsb[12 + ujj] + gxb[12 + ujj];
            float c = sigm_f(gf) * creg + sigm_f(gi) * tanh_f(gg);
            creg = c;
            float h = sigm_f(go) * tanh_f(c);
            hout[(size_t)(s * 64 + ubat) * 512 + (dir << 8) + j0 + ujj] = h;
            float hB = __shfl_down_sync(0xffffffffu, h, 1);
            float hC = __shfl_down_sync(0xffffffffu, h, 2);
            float hD = __shfl_down_sync(0xffffffffu, h, 3);
            if (t < 511 && ujj == 0) {
                __half2 lo2 = __floats2half2_rn(h, hB);
                __half2 hi2 = __floats2half2_rn(hC, hD);
                uint2 pk;
                pk.x = *(unsigned*)&lo2; pk.y = *(unsigned*)&hi2;
                *(uint2*)(hdst + ubat * 256 + j0) = pk;
            }
        }
        if (t < 511) { ++kbar; gbar(tid, grp, kbar); }
    }
}

__global__ void score_kernel(const float* __restrict__ wlin,
                             const float* __restrict__ blin,
                             const float* __restrict__ labels,
                             const int* __restrict__ masks,
                             float* __restrict__ outs) {
    int w = blockIdx.x * 8 + (threadIdx.x >> 5);
    int lane = threadIdx.x & 31;
    int s = w >> 6, b = w & 63;
    const float* hp = g_h2 + (size_t)w * 512;
    float acc = 0.0f;
#pragma unroll
    for (int j = lane; j < 256; j += 32)
        acc += 0.5f * (hp[j] + hp[256 + j]) * wlin[j];
#pragma unroll
    for (int d = 16; d; d >>= 1) acc += __shfl_xor_sync(0xffffffffu, acc, d);
    if (lane == 0) {
        float sc = sigm(acc + blin[0]);
        int oi = b * S_ + s;
        outs[oi] = sc;
        float df = sc - labels[oi];
        g_err[oi] = df * df * (float)masks[oi];
    }
}

__global__ void loss_kernel(const int* __restrict__ masks,
                            float* __restrict__ out, int out_size) {
    __shared__ float sr[64];
    int b = threadIdx.x;
    if (b < 64) {
        float se = 0.0f, sm = 0.0f;
        for (int s = 0; s < S_; ++s) {
            se += g_err[b * S_ + s];
            sm += (float)masks[b * S_ + s];
        }
        sr[b] = se / sm;
    }
    __syncthreads();
    if (threadIdx.x == 0 && out_size > M_) {
        float t = 0.0f;
        for (int i = 0; i < 64; ++i) t += sr[i];
        out[M_] = t / 64.0f;
    }
}

extern "C" void kernel_launch(void* const* d_in, const int* in_sizes, int n_in,
                              void* d_out, int out_size) {
    const int*   ids    = (const int*)d_in[0];
    const float* labels = (const float*)d_in[1];
    const int*   masks  = (const int*)d_in[2];
    const float* emb    = (const float*)d_in[3];
    const float* wih0f = (const float*)d_in[4];
    const float* whh0f = (const float*)d_in[5];
    const float* bih0f = (const float*)d_in[6];
    const float* bhh0f = (const float*)d_in[7];
    const float* wih0b = (const float*)d_in[8];
    const float* whh0b = (const float*)d_in[9];
    const float* bih0b = (const float*)d_in[10];
    const float* bhh0b = (const float*)d_in[11];
    const float* wih1f = (const float*)d_in[12];
    const float* whh1f = (const float*)d_in[13];
    const float* bih1f = (const float*)d_in[14];
    const float* bhh1f = (const float*)d_in[15];
    const float* wih1b = (const float*)d_in[16];
    const float* whh1b = (const float*)d_in[17];
    const float* bih1b = (const float*)d_in[18];
    const float* bhh1b = (const float*)d_in[19];
    const float* wlin  = (const float*)d_in[20];
    const float* blin  = (const float*)d_in[21];
    float* out = (float*)d_out;

    static bool attr_done = false;
    if (!attr_done) {
        cudaFuncSetAttribute(lstm_kernel, cudaFuncAttributeMaxDynamicSharedMemorySize,
                             LSTM_SMEM_BYTES);
        attr_done = true;
    }

    gather_kernel<<<M_, 128>>>(ids, emb);
    padw_kernel<<<2048, 128>>>(wih0f, wih0b);

    dim3 gg(16, 256);
    sgemm_kernel<<<gg, 256>>>(0, 0, nullptr, bih0f, bhh0f);
    sgemm_kernel<<<gg, 256>>>(0, 1, nullptr, bih0b, bhh0b);

    zerocnt_kernel<<<1, 256>>>();
    lstm_kernel<<<128, 256, LSTM_SMEM_BYTES>>>(0, whh0f, whh0b);

    sgemm_kernel<<<gg, 256>>>(1, 0, wih1f, bih1f, bhh1f);
    sgemm_kernel<<<gg, 256>>>(1, 1, wih1b, bih1b, bhh1b);

    zerocnt_kernel<<<1, 256>>>();
    lstm_kernel<<<128, 256, LSTM_SMEM_BYTES>>>(1, whh1f, whh1b);

    score_kernel<<<M_ / 8, 256>>>(wlin, blin, labels, masks, out);
    loss_kernel<<<1, 64>>>(masks, out, out_size);
}